// round 10
// baseline (speedup 1.0000x reference)
#include <cuda_runtime.h>
#include <cuda_bf16.h>

// CrossNet collapsed:
//   out = x0 * a3 + Bsum
//   a_{l+1} = a_l + (a_l * d_l + c_l);  d_l = dot(x0_row, W[l]) per-row;
//   c_l = dot(Bsum_l, W[l]) row-independent; Bsum = B0+B1+B2.
//
// PERSISTENT version: 608 CTAs (152 SMs x 4) grid-stride over 4096 row-groups
// (R=4 rows each). W/B are loaded into registers ONCE per CTA (the per-block
// reload was 43% of all L1 wavefronts in R6). Loop body touches DRAM only for
// x-in and out. One barrier per iteration via double-buffered smem exchange.

#define DIMV 256   // float4s per row (DIM = 1024)
#define R 4        // rows per group

__device__ __forceinline__ float dot4(float4 a, float4 b) {
    return fmaf(a.x, b.x, fmaf(a.y, b.y, fmaf(a.z, b.z, a.w * b.w)));
}

__global__ __launch_bounds__(256, 4) void crossnet_kernel(
    const float4* __restrict__ x0,
    const float4* __restrict__ W,
    const float4* __restrict__ Bm,
    float4* __restrict__ out,
    int ngroups)
{
    __shared__ float sd[2][8][16];   // [buf][warp][chain], padded stride 16
    __shared__ float scc[2][8];      // prologue c1/c2 partials per warp

    const int t = threadIdx.x;
    const int lane = t & 31;
    const int warp = t >> 5;

    // ---- once per CTA: W/B -> registers, bsum, C1/C2 ----
    float4 w0 = W[t];
    float4 w1 = W[DIMV + t];
    float4 w2 = W[2 * DIMV + t];
    float4 bsum;
    float c1p, c2p;
    {
        float4 b0 = Bm[t];
        float4 b1 = Bm[DIMV + t];
        float4 b2 = Bm[2 * DIMV + t];
        float4 b01 = make_float4(b0.x + b1.x, b0.y + b1.y, b0.z + b1.z, b0.w + b1.w);
        bsum = make_float4(b01.x + b2.x, b01.y + b2.y, b01.z + b2.z, b01.w + b2.w);
        c1p = dot4(b0, w1);    // c1 partial
        c2p = dot4(b01, w2);   // c2 partial
    }
#pragma unroll
    for (int o = 16; o > 0; o >>= 1) {
        c1p += __shfl_xor_sync(0xffffffffu, c1p, o);
        c2p += __shfl_xor_sync(0xffffffffu, c2p, o);
    }
    if (lane == 0) { scc[0][warp] = c1p; scc[1][warp] = c2p; }
    __syncthreads();
    float C1 = 0.f, C2 = 0.f;
#pragma unroll
    for (int w = 0; w < 8; ++w) { C1 += scc[0][w]; C2 += scc[1][w]; }
    // scc is never written again; the loop barrier provides all later ordering.

    // ---- persistent loop over row-groups ----
    int buf = 0;
    for (int g = blockIdx.x; g < ngroups; g += gridDim.x) {
        const size_t base = (size_t)g * (R * DIMV) + t;

        // the only DRAM reads (front-batched, 4 independent LDG.128)
        float4 x[R];
#pragma unroll
        for (int r = 0; r < R; ++r) x[r] = x0[base + r * DIMV];

        // 12 dot chains: q = 3r + l
        float v[12];
#pragma unroll
        for (int r = 0; r < R; ++r) {
            v[3 * r + 0] = dot4(x[r], w0);
            v[3 * r + 1] = dot4(x[r], w1);
            v[3 * r + 2] = dot4(x[r], w2);
        }
#pragma unroll
        for (int o = 16; o > 0; o >>= 1) {
#pragma unroll
            for (int q = 0; q < 12; ++q)
                v[q] += __shfl_xor_sync(0xffffffffu, v[q], o);
        }

        if (lane < 12) sd[buf][warp][lane] = v[lane];
        __syncthreads();   // the only barrier in the loop

        float S = 0.0f;
        if (lane < 12) {
#pragma unroll
            for (int w = 0; w < 8; ++w) S += sd[buf][w][lane];   // conflict-free
        }

        // lanes 0..3 assemble row scalars and run the 6-FLOP recurrence
        float d0 = __shfl_sync(0xffffffffu, S, (lane < R) ? 3 * lane + 0 : 0);
        float d1 = __shfl_sync(0xffffffffu, S, (lane < R) ? 3 * lane + 1 : 0);
        float d2 = __shfl_sync(0xffffffffu, S, (lane < R) ? 3 * lane + 2 : 0);

        float a = 1.0f;
        {
            float s = a * d0;        a += s;   // c0 == 0 exactly
            s = fmaf(a, d1, C1);     a += s;
            s = fmaf(a, d2, C2);     a += s;
        }
        const float a0 = __shfl_sync(0xffffffffu, a, 0);
        const float a1 = __shfl_sync(0xffffffffu, a, 1);
        const float a2 = __shfl_sync(0xffffffffu, a, 2);
        const float a3 = __shfl_sync(0xffffffffu, a, 3);
        const float ar[R] = {a0, a1, a2, a3};

        // the only DRAM writes
#pragma unroll
        for (int r = 0; r < R; ++r) {
            float4 o;
            o.x = fmaf(x[r].x, ar[r], bsum.x);
            o.y = fmaf(x[r].y, ar[r], bsum.y);
            o.z = fmaf(x[r].z, ar[r], bsum.z);
            o.w = fmaf(x[r].w, ar[r], bsum.w);
            out[base + r * DIMV] = o;
        }
        buf ^= 1;
    }
}

extern "C" void kernel_launch(void* const* d_in, const int* in_sizes, int n_in,
                              void* d_out, int out_size)
{
    const float4* x0 = (const float4*)d_in[0];
    const float4* W  = (const float4*)d_in[1];
    const float4* B  = (const float4*)d_in[2];
    float4* out = (float4*)d_out;

    const int batch = in_sizes[0] / 1024;   // 16384
    const int ngroups = batch / R;          // 4096
    const int blocks = 152 * 4;             // persistent: 4 CTAs/SM on GB300

    crossnet_kernel<<<blocks, 256>>>(x0, W, B, out, ngroups);
}